// round 3
// baseline (speedup 1.0000x reference)
#include <cuda_runtime.h>

#define N_NODES 50000
#define N_EDGES 1200000
#define DIM 64

// Scratch (allocation-free: __device__ globals), 16B-aligned for float4 access
__device__ __align__(16) float g_Henc[N_NODES * DIM];   // encoder output per layer
__device__ __align__(16) float g_agg [N_NODES * DIM];   // scatter-add accumulator
__device__ __align__(16) float g_H   [N_NODES * DIM];   // layer output
__device__ __align__(16) float g_norm[N_EDGES];         // per-edge dis[u]*dis[v]
__device__ __align__(16) float g_dis [N_NODES];         // (deg+1)^-0.5
__device__ __align__(16) int   g_deg [N_NODES];
__device__ __align__(16) int   g_u   [N_EDGES];
__device__ __align__(16) int   g_v   [N_EDGES];
__device__ __align__(16) float g_sum64[DIM];
__device__ int g_is32;   // 1 if edge_index is int32 on device, 0 if int64

// ---------------------------------------------------------------------------
// Probe edge_index dtype: if int64, all values < 50000 so every high word is 0.
// If int32, "high words" are random indices -> almost surely nonzero.
__global__ void k_probe(const unsigned long long* __restrict__ ei) {
    int t = threadIdx.x;
    unsigned int any = 0;
    for (int i = t; i < 2048; i += 256)
        any |= (unsigned int)(ei[i] >> 32);
    __shared__ unsigned int s;
    if (t == 0) s = 0u;
    __syncthreads();
    atomicOr(&s, any);
    __syncthreads();
    if (t == 0) g_is32 = (s != 0u) ? 1 : 0;
}

// Init: zero agg / deg / sum64
__global__ void __launch_bounds__(256) k_zero() {
    int i = blockIdx.x * 256 + threadIdx.x;
    if (i < N_NODES * DIM / 4)
        ((float4*)g_agg)[i] = make_float4(0.f, 0.f, 0.f, 0.f);
    if (i < N_NODES) g_deg[i] = 0;
    if (i < DIM)     g_sum64[i] = 0.f;
}

// Decode edge index (int32 or int64 layout) -> int32 u/v, accumulate degree(u)
__global__ void __launch_bounds__(256) k_prep(const void* __restrict__ eiv) {
    int i = blockIdx.x * 256 + threadIdx.x;
    if (i >= N_EDGES) return;
    int uu, vv;
    if (g_is32) {
        const int* e = (const int*)eiv;
        uu = e[i];
        vv = e[N_EDGES + i];
    } else {
        const long long* e = (const long long*)eiv;
        uu = (int)e[i];
        vv = (int)e[N_EDGES + i];
    }
    // clamp so bad data can never produce a wild atomic address
    uu = min(max(uu, 0), N_NODES - 1);
    vv = min(max(vv, 0), N_NODES - 1);
    g_u[i] = uu;
    g_v[i] = vv;
    atomicAdd(&g_deg[uu], 1);
}

__global__ void __launch_bounds__(256) k_dis() {
    int i = blockIdx.x * 256 + threadIdx.x;
    if (i < N_NODES)
        g_dis[i] = rsqrtf((float)g_deg[i] + 1.0f);
}

__global__ void __launch_bounds__(256) k_norm() {
    int i = blockIdx.x * 256 + threadIdx.x;
    if (i < N_EDGES)
        g_norm[i] = g_dis[g_u[i]] * g_dis[g_v[i]];
}

// ---------------------------------------------------------------------------
// 64x64 GEMM core: one row per thread, W staged in shared (warp-uniform
// broadcast LDS.128 reads), 64 fp32 accumulators per thread.
__device__ __forceinline__ void gemm_row_core(
    const float4* __restrict__ xr,   // row of X (16 x float4)
    float4*       __restrict__ ar,   // row of agg (nullptr if not used)
    const float4* __restrict__ Ws,   // shared W, [64][16] float4
    const float*  __restrict__ Bs,   // shared bias [64]
    float4*       __restrict__ yr,   // output row (16 x float4)
    bool add_agg, bool do_relu)
{
    float4 acc[16];
#pragma unroll
    for (int j = 0; j < 16; j++)
        acc[j] = make_float4(Bs[4*j], Bs[4*j+1], Bs[4*j+2], Bs[4*j+3]);

#pragma unroll 1
    for (int kk = 0; kk < 16; kk++) {
        float4 hv = xr[kk];
        if (add_agg) {
            float4 a = ar[kk];
            hv.x += a.x; hv.y += a.y; hv.z += a.z; hv.w += a.w;
            ar[kk] = make_float4(0.f, 0.f, 0.f, 0.f);   // reset agg for next layer
        }
#pragma unroll
        for (int kc = 0; kc < 4; kc++) {
            float hk = (kc == 0) ? hv.x : (kc == 1) ? hv.y : (kc == 2) ? hv.z : hv.w;
            const float4* wrow = Ws + (kk * 4 + kc) * 16;
#pragma unroll
            for (int j = 0; j < 16; j++) {
                float4 w = wrow[j];
                acc[j].x = fmaf(hk, w.x, acc[j].x);
                acc[j].y = fmaf(hk, w.y, acc[j].y);
                acc[j].z = fmaf(hk, w.z, acc[j].z);
                acc[j].w = fmaf(hk, w.w, acc[j].w);
            }
        }
    }

#pragma unroll
    for (int j = 0; j < 16; j++) {
        float4 o = acc[j];
        if (do_relu) {
            o.x = fmaxf(o.x, 0.f); o.y = fmaxf(o.y, 0.f);
            o.z = fmaxf(o.z, 0.f); o.w = fmaxf(o.w, 0.f);
        }
        yr[j] = o;
    }
}

// Encoder GEMM: g_Henc = src @ W + b. src = X (layer 0) or g_H (layers 1,2).
__global__ void __launch_bounds__(128) k_gemm_enc(
    const float* __restrict__ X,
    const float* __restrict__ W,
    const float* __restrict__ B,
    int use_gH)
{
    __shared__ float4 Ws[1024];
    __shared__ float  Bs[64];
    int tid = threadIdx.x;
    const float4* W4 = (const float4*)W;
#pragma unroll
    for (int i = 0; i < 8; i++) Ws[tid + 128 * i] = W4[tid + 128 * i];
    if (tid < 64) Bs[tid] = B[tid];
    __syncthreads();

    int row = blockIdx.x * 128 + tid;
    if (row >= N_NODES) return;
    const float* src = use_gH ? g_H : X;
    gemm_row_core((const float4*)(src + row * DIM), nullptr, Ws, Bs,
                  (float4*)(g_Henc + row * DIM), false, false);
}

// Update GEMM: g_H = relu((g_agg + g_Henc) @ W + b); resets g_agg to 0
__global__ void __launch_bounds__(128) k_gemm_upd(
    const float* __restrict__ W,
    const float* __restrict__ B)
{
    __shared__ float4 Ws[1024];
    __shared__ float  Bs[64];
    int tid = threadIdx.x;
    const float4* W4 = (const float4*)W;
#pragma unroll
    for (int i = 0; i < 8; i++) Ws[tid + 128 * i] = W4[tid + 128 * i];
    if (tid < 64) Bs[tid] = B[tid];
    __syncthreads();

    int row = blockIdx.x * 128 + tid;
    if (row >= N_NODES) return;
    gemm_row_core((const float4*)(g_Henc + row * DIM),
                  (float4*)(g_agg + row * DIM), Ws, Bs,
                  (float4*)(g_H + row * DIM), true, true);
}

// ---------------------------------------------------------------------------
// Edge scatter: agg[v] += norm[e] * Henc[u]. 16 threads (float4 each) per edge.
__global__ void __launch_bounds__(256) k_edge() {
    int idx = blockIdx.x * 256 + threadIdx.x;
    int e = idx >> 4;
    if (e >= N_EDGES) return;
    int c = idx & 15;
    int uu = g_u[e];
    int vv = g_v[e];
    float nw = g_norm[e];
    float4 g = ((const float4*)g_Henc)[uu * 16 + c];
    float* dst = g_agg + vv * DIM + c * 4;
    atomicAdd(dst + 0, nw * g.x);
    atomicAdd(dst + 1, nw * g.y);
    atomicAdd(dst + 2, nw * g.z);
    atomicAdd(dst + 3, nw * g.w);
}

// ---------------------------------------------------------------------------
// Readout: column sums of g_H into g_sum64
__global__ void __launch_bounds__(256) k_sum() {
    int tid = threadIdx.x;
    int c = tid & 63;
    int g = tid >> 6;           // 0..3 row-lanes per block
    float local = 0.f;
    for (int row = blockIdx.x * 4 + g; row < N_NODES; row += gridDim.x * 4)
        local += g_H[row * DIM + c];
    __shared__ float s[256];
    s[tid] = local;
    __syncthreads();
    if (tid < 64)
        atomicAdd(&g_sum64[tid], s[tid] + s[tid + 64] + s[tid + 128] + s[tid + 192]);
}

// out[0] = dot(sum64, out_w)/N + out_b
__global__ void k_final(const float* __restrict__ out_w,
                        const float* __restrict__ out_b,
                        float* __restrict__ out)
{
    int t = threadIdx.x;  // 32 threads
    float p = g_sum64[t] * out_w[t] + g_sum64[t + 32] * out_w[t + 32];
#pragma unroll
    for (int o = 16; o; o >>= 1) p += __shfl_down_sync(0xffffffffu, p, o);
    if (t == 0) out[0] = p / (float)N_NODES + out_b[0];
}

// ---------------------------------------------------------------------------
extern "C" void kernel_launch(void* const* d_in, const int* in_sizes, int n_in,
                              void* d_out, int out_size)
{
    const float* H  = (const float*)d_in[0];
    const void*  ei = d_in[1];
    // d_in[2] = E (unused by reference GCN path)
    const float* enc_w[3] = {(const float*)d_in[3],  (const float*)d_in[7],  (const float*)d_in[11]};
    const float* enc_b[3] = {(const float*)d_in[4],  (const float*)d_in[8],  (const float*)d_in[12]};
    const float* upd_w[3] = {(const float*)d_in[5],  (const float*)d_in[9],  (const float*)d_in[13]};
    const float* upd_b[3] = {(const float*)d_in[6],  (const float*)d_in[10], (const float*)d_in[14]};
    const float* out_w = (const float*)d_in[15];
    const float* out_b = (const float*)d_in[16];
    float* out = (float*)d_out;

    const int EB = (N_EDGES + 255) / 256;             // 4688
    const int NB = (N_NODES + 255) / 256;             // 196
    const int ZB = (N_NODES * DIM / 4 + 255) / 256;   // 3125
    const int GB = (N_NODES + 127) / 128;             // 391
    const int SB = (N_EDGES * 16 + 255) / 256;        // 75000

    k_probe<<<1, 256>>>((const unsigned long long*)ei);
    k_zero <<<ZB, 256>>>();
    k_prep <<<EB, 256>>>(ei);
    k_dis  <<<NB, 256>>>();
    k_norm <<<EB, 256>>>();

    for (int l = 0; l < 3; l++) {
        k_gemm_enc<<<GB, 128>>>(H, enc_w[l], enc_b[l], l > 0 ? 1 : 0);
        k_edge    <<<SB, 256>>>();
        k_gemm_upd<<<GB, 128>>>(upd_w[l], upd_b[l]);
    }

    k_sum  <<<512, 256>>>();
    k_final<<<1, 32>>>(out_w, out_b, out);
}

// round 4
// speedup vs baseline: 2.0148x; 2.0148x over previous
#include <cuda_runtime.h>

#define N_NODES 50000
#define N_EDGES 1200000
#define DIM 64

// Scratch (allocation-free: __device__ globals), 16B-aligned for float4 access
__device__ __align__(16) float g_Henc[N_NODES * DIM];   // encoder output per layer
__device__ __align__(16) float g_agg [N_NODES * DIM];   // pulled aggregation
__device__ __align__(16) float g_H   [N_NODES * DIM];   // layer output
__device__ __align__(16) float g_dis [N_NODES];         // (deg+1)^-0.5
__device__ __align__(16) int   g_deg [N_NODES];         // out-degree over u
__device__ __align__(16) int   g_cnt [N_NODES];         // in-degree over v
__device__ __align__(16) int   g_fill[N_NODES];         // fill cursor per v
__device__ __align__(16) int   g_rowstart[N_NODES + 1]; // CSR row offsets (by v)
__device__ __align__(16) int2  g_uv  [N_EDGES];         // decoded (u,v)
__device__ __align__(16) int2  g_csr [N_EDGES];         // (u, float_bits(norm)) sorted by v
__device__ __align__(16) float g_sum64[DIM];
__device__ int g_is32;   // 1 if edge_index is int32 on device, 0 if int64

// ---------------------------------------------------------------------------
// Probe edge_index dtype: if int64, all values < 50000 so every high word is 0.
__global__ void k_probe(const unsigned long long* __restrict__ ei) {
    int t = threadIdx.x;
    unsigned int any = 0;
    for (int i = t; i < 2048; i += 256)
        any |= (unsigned int)(ei[i] >> 32);
    __shared__ unsigned int s;
    if (t == 0) s = 0u;
    __syncthreads();
    atomicOr(&s, any);
    __syncthreads();
    if (t == 0) g_is32 = (s != 0u) ? 1 : 0;
}

// Zero counters
__global__ void __launch_bounds__(256) k_zero() {
    int i = blockIdx.x * 256 + threadIdx.x;
    if (i < N_NODES) { g_deg[i] = 0; g_cnt[i] = 0; g_fill[i] = 0; }
    if (i < DIM)     g_sum64[i] = 0.f;
}

// Decode edge index -> int2 uv, histogram out-degree(u) and in-degree(v)
__global__ void __launch_bounds__(256) k_prep(const void* __restrict__ eiv) {
    int i = blockIdx.x * 256 + threadIdx.x;
    if (i >= N_EDGES) return;
    int uu, vv;
    if (g_is32) {
        const int* e = (const int*)eiv;
        uu = e[i];
        vv = e[N_EDGES + i];
    } else {
        const long long* e = (const long long*)eiv;
        uu = (int)e[i];
        vv = (int)e[N_EDGES + i];
    }
    uu = min(max(uu, 0), N_NODES - 1);
    vv = min(max(vv, 0), N_NODES - 1);
    g_uv[i] = make_int2(uu, vv);
    atomicAdd(&g_deg[uu], 1);
    atomicAdd(&g_cnt[vv], 1);
}

__global__ void __launch_bounds__(256) k_dis() {
    int i = blockIdx.x * 256 + threadIdx.x;
    if (i < N_NODES)
        g_dis[i] = rsqrtf((float)g_deg[i] + 1.0f);
}

// One-block exclusive scan of g_cnt -> g_rowstart (two-pass, no per-thread arrays)
__global__ void __launch_bounds__(1024) k_scan() {
    const int CH = (N_NODES + 1023) / 1024;  // 49
    __shared__ int sh[1024];
    int t = threadIdx.x;
    int base = t * CH;
    int tot = 0;
    for (int i = 0; i < CH; i++) {
        int j = base + i;
        if (j < N_NODES) tot += g_cnt[j];
    }
    sh[t] = tot;
    __syncthreads();
    for (int o = 1; o < 1024; o <<= 1) {
        int v = (t >= o) ? sh[t - o] : 0;
        __syncthreads();
        sh[t] += v;
        __syncthreads();
    }
    int run = (t > 0) ? sh[t - 1] : 0;
    for (int i = 0; i < CH; i++) {
        int j = base + i;
        if (j < N_NODES) {
            g_rowstart[j] = run;
            run += g_cnt[j];
        }
    }
    if (t == 1023) g_rowstart[N_NODES] = run;
}

// Scatter edges into CSR slots (sorted by v), weight = dis[u]*dis[v]
__global__ void __launch_bounds__(256) k_fill() {
    int i = blockIdx.x * 256 + threadIdx.x;
    if (i >= N_EDGES) return;
    int2 uv = g_uv[i];
    float w = g_dis[uv.x] * g_dis[uv.y];
    int pos = g_rowstart[uv.y] + atomicAdd(&g_fill[uv.y], 1);
    g_csr[pos] = make_int2(uv.x, __float_as_int(w));
}

// ---------------------------------------------------------------------------
// 64x64 GEMM core: one row per thread, W staged in shared (warp-uniform
// broadcast LDS.128 reads), 64 fp32 accumulators per thread.
__device__ __forceinline__ void gemm_row_core(
    const float4* __restrict__ xr,   // row of X (16 x float4)
    const float4* __restrict__ ar,   // row of agg (nullptr if not used)
    const float4* __restrict__ Ws,   // shared W, [64][16] float4
    const float*  __restrict__ Bs,   // shared bias [64]
    float4*       __restrict__ yr,   // output row (16 x float4)
    bool add_agg, bool do_relu)
{
    float4 acc[16];
#pragma unroll
    for (int j = 0; j < 16; j++)
        acc[j] = make_float4(Bs[4*j], Bs[4*j+1], Bs[4*j+2], Bs[4*j+3]);

#pragma unroll 1
    for (int kk = 0; kk < 16; kk++) {
        float4 hv = xr[kk];
        if (add_agg) {
            float4 a = ar[kk];
            hv.x += a.x; hv.y += a.y; hv.z += a.z; hv.w += a.w;
        }
#pragma unroll
        for (int kc = 0; kc < 4; kc++) {
            float hk = (kc == 0) ? hv.x : (kc == 1) ? hv.y : (kc == 2) ? hv.z : hv.w;
            const float4* wrow = Ws + (kk * 4 + kc) * 16;
#pragma unroll
            for (int j = 0; j < 16; j++) {
                float4 w = wrow[j];
                acc[j].x = fmaf(hk, w.x, acc[j].x);
                acc[j].y = fmaf(hk, w.y, acc[j].y);
                acc[j].z = fmaf(hk, w.z, acc[j].z);
                acc[j].w = fmaf(hk, w.w, acc[j].w);
            }
        }
    }

#pragma unroll
    for (int j = 0; j < 16; j++) {
        float4 o = acc[j];
        if (do_relu) {
            o.x = fmaxf(o.x, 0.f); o.y = fmaxf(o.y, 0.f);
            o.z = fmaxf(o.z, 0.f); o.w = fmaxf(o.w, 0.f);
        }
        yr[j] = o;
    }
}

// Encoder GEMM: g_Henc = src @ W + b. src = X (layer 0) or g_H (layers 1,2).
__global__ void __launch_bounds__(128) k_gemm_enc(
    const float* __restrict__ X,
    const float* __restrict__ W,
    const float* __restrict__ B,
    int use_gH)
{
    __shared__ float4 Ws[1024];
    __shared__ float  Bs[64];
    int tid = threadIdx.x;
    const float4* W4 = (const float4*)W;
#pragma unroll
    for (int i = 0; i < 8; i++) Ws[tid + 128 * i] = W4[tid + 128 * i];
    if (tid < 64) Bs[tid] = B[tid];
    __syncthreads();

    int row = blockIdx.x * 128 + tid;
    if (row >= N_NODES) return;
    const float* src = use_gH ? g_H : X;
    gemm_row_core((const float4*)(src + row * DIM), nullptr, Ws, Bs,
                  (float4*)(g_Henc + row * DIM), false, false);
}

// Update GEMM: g_H = relu((g_agg + g_Henc) @ W + b)
__global__ void __launch_bounds__(128) k_gemm_upd(
    const float* __restrict__ W,
    const float* __restrict__ B)
{
    __shared__ float4 Ws[1024];
    __shared__ float  Bs[64];
    int tid = threadIdx.x;
    const float4* W4 = (const float4*)W;
#pragma unroll
    for (int i = 0; i < 8; i++) Ws[tid + 128 * i] = W4[tid + 128 * i];
    if (tid < 64) Bs[tid] = B[tid];
    __syncthreads();

    int row = blockIdx.x * 128 + tid;
    if (row >= N_NODES) return;
    gemm_row_core((const float4*)(g_Henc + row * DIM),
                  (const float4*)(g_agg + row * DIM), Ws, Bs,
                  (float4*)(g_H + row * DIM), true, true);
}

// ---------------------------------------------------------------------------
// Pull aggregation: agg[v] = sum_{e in CSR row v} w_e * Henc[u_e].
// 16 threads per node, one float4 lane each. No atomics, deterministic layout.
__global__ void __launch_bounds__(256) k_agg() {
    int idx = blockIdx.x * 256 + threadIdx.x;
    int node = idx >> 4;
    if (node >= N_NODES) return;
    int c = idx & 15;
    int s = g_rowstart[node];
    int e = g_rowstart[node + 1];
    float4 acc = make_float4(0.f, 0.f, 0.f, 0.f);
    const float4* __restrict__ Henc4 = (const float4*)g_Henc;
    for (int i = s; i < e; i++) {
        int2 ed = g_csr[i];                 // broadcast within half-warp (L1)
        float w = __int_as_float(ed.y);
        float4 g = Henc4[ed.x * 16 + c];
        acc.x = fmaf(w, g.x, acc.x);
        acc.y = fmaf(w, g.y, acc.y);
        acc.z = fmaf(w, g.z, acc.z);
        acc.w = fmaf(w, g.w, acc.w);
    }
    ((float4*)g_agg)[node * 16 + c] = acc;
}

// ---------------------------------------------------------------------------
// Readout: column sums of g_H into g_sum64
__global__ void __launch_bounds__(256) k_sum() {
    int tid = threadIdx.x;
    int c = tid & 63;
    int g = tid >> 6;           // 0..3 row-lanes per block
    float local = 0.f;
    for (int row = blockIdx.x * 4 + g; row < N_NODES; row += gridDim.x * 4)
        local += g_H[row * DIM + c];
    __shared__ float s[256];
    s[tid] = local;
    __syncthreads();
    if (tid < 64)
        atomicAdd(&g_sum64[tid], s[tid] + s[tid + 64] + s[tid + 128] + s[tid + 192]);
}

// out[0] = dot(sum64, out_w)/N + out_b
__global__ void k_final(const float* __restrict__ out_w,
                        const float* __restrict__ out_b,
                        float* __restrict__ out)
{
    int t = threadIdx.x;  // 32 threads
    float p = g_sum64[t] * out_w[t] + g_sum64[t + 32] * out_w[t + 32];
#pragma unroll
    for (int o = 16; o; o >>= 1) p += __shfl_down_sync(0xffffffffu, p, o);
    if (t == 0) out[0] = p / (float)N_NODES + out_b[0];
}

// ---------------------------------------------------------------------------
extern "C" void kernel_launch(void* const* d_in, const int* in_sizes, int n_in,
                              void* d_out, int out_size)
{
    const float* H  = (const float*)d_in[0];
    const void*  ei = d_in[1];
    // d_in[2] = E (unused by reference GCN path)
    const float* enc_w[3] = {(const float*)d_in[3],  (const float*)d_in[7],  (const float*)d_in[11]};
    const float* enc_b[3] = {(const float*)d_in[4],  (const float*)d_in[8],  (const float*)d_in[12]};
    const float* upd_w[3] = {(const float*)d_in[5],  (const float*)d_in[9],  (const float*)d_in[13]};
    const float* upd_b[3] = {(const float*)d_in[6],  (const float*)d_in[10], (const float*)d_in[14]};
    const float* out_w = (const float*)d_in[15];
    const float* out_b = (const float*)d_in[16];
    float* out = (float*)d_out;

    const int EB = (N_EDGES + 255) / 256;             // 4688
    const int NB = (N_NODES + 255) / 256;             // 196
    const int GB = (N_NODES + 127) / 128;             // 391
    const int AB = (N_NODES * 16 + 255) / 256;        // 3125

    k_probe<<<1, 256>>>((const unsigned long long*)ei);
    k_zero <<<NB, 256>>>();
    k_prep <<<EB, 256>>>(ei);
    k_dis  <<<NB, 256>>>();
    k_scan <<<1, 1024>>>();
    k_fill <<<EB, 256>>>();

    for (int l = 0; l < 3; l++) {
        k_gemm_enc<<<GB, 128>>>(H, enc_w[l], enc_b[l], l > 0 ? 1 : 0);
        k_agg     <<<AB, 256>>>();
        k_gemm_upd<<<GB, 128>>>(upd_w[l], upd_b[l]);
    }

    k_sum  <<<512, 256>>>();
    k_final<<<1, 32>>>(out_w, out_b, out);
}